// round 4
// baseline (speedup 1.0000x reference)
#include <cuda_runtime.h>
#include <cuda_bf16.h>

// Problem constants (from reference: B=64, N=1000, K=128)
static constexpr int BATCH   = 64;
static constexpr int NN      = 1000;
static constexpr int KK      = 128;
static constexpr int THREADS = 1024;
static constexpr int ITEMS   = BATCH * KK;          // 8192
static constexpr int PER_T   = ITEMS / THREADS;     // 8

// Single fused kernel: dedupe + gather + full reduction, one block.
__global__ __launch_bounds__(THREADS, 1)
void masked_loss_fused(const float* __restrict__ y_true,
                       const float* __restrict__ y_pred,
                       const void*  __restrict__ rows,
                       const void*  __restrict__ cols,
                       float* __restrict__ out)
{
    __shared__ int   sr[KK];
    __shared__ int   sc[KK];
    __shared__ int   skeep[KK];
    __shared__ float warp_sums[THREADS / 32];

    const int t = threadIdx.x;

    // ---- dtype detection: reference says int64, JAX x64-off delivers int32 ----
    // Interpret as int64; valid iff ALL K values of both arrays are in [0, NN).
    int in_range = 1;
    if (t < KK) {
        const long long r64 = ((const long long*)rows)[t];
        const long long c64 = ((const long long*)cols)[t];
        in_range = (r64 >= 0 && r64 < NN && c64 >= 0 && c64 < NN) ? 1 : 0;
    }
    const int use_i64 = __syncthreads_and(in_range);

    if (t < KK) {
        if (use_i64) {
            sr[t] = (int)((const long long*)rows)[t];
            sc[t] = (int)((const long long*)cols)[t];
        } else {
            sr[t] = ((const int*)rows)[t];
            sc[t] = ((const int*)cols)[t];
        }
    }
    __syncthreads();

    // ---- dedupe (set semantics: first occurrence wins) ----
    if (t < KK) {
        const int r = sr[t], c = sc[t];
        int keep = 1;
        for (int j = 0; j < t; ++j) {
            if (sr[j] == r && sc[j] == c) { keep = 0; break; }
        }
        skeep[t] = keep;
    }
    __syncthreads();

    // ---- gather + accumulate: each thread owns PER_T (batch,pair) items ----
    float acc = 0.0f;
    #pragma unroll
    for (int k = 0; k < PER_T; ++k) {
        const int item = t + k * THREADS;       // 0..8191
        const int b    = item >> 7;             // /KK
        const int p    = item & (KK - 1);       // %KK
        if (skeep[p]) {
            const size_t base = (size_t)b * (NN * NN) + (size_t)sr[p] * NN + sc[p];
            const float d = __ldg(&y_true[base]) - __ldg(&y_pred[base]);
            acc += d * d;
        }
    }

    // ---- block reduction ----
    #pragma unroll
    for (int off = 16; off > 0; off >>= 1)
        acc += __shfl_xor_sync(0xffffffffu, acc, off);
    if ((t & 31) == 0) warp_sums[t >> 5] = acc;
    __syncthreads();

    if (t < 32) {
        float v = warp_sums[t];
        #pragma unroll
        for (int off = 16; off > 0; off >>= 1)
            v += __shfl_xor_sync(0xffffffffu, v, off);
        if (t == 0) out[0] = v;
    }
}

extern "C" void kernel_launch(void* const* d_in, const int* in_sizes, int n_in,
                              void* d_out, int out_size)
{
    const float* y_true = (const float*)d_in[0];
    const float* y_pred = (const float*)d_in[1];
    masked_loss_fused<<<1, THREADS>>>(y_true, y_pred, d_in[2], d_in[3],
                                      (float*)d_out);
}

// round 5
// speedup vs baseline: 1.2829x; 1.2829x over previous
#include <cuda_runtime.h>
#include <cuda_bf16.h>

// Problem constants (from reference: B=64, N=1000, K=128)
static constexpr int BATCH = 64;
static constexpr int NN    = 1000;
static constexpr int KK    = 128;

__device__ float        g_partials[BATCH];
__device__ unsigned int g_count = 0;   // self-resetting ticket counter

// One block per batch. Gather + per-block reduce, then the last block to
// finish performs the deterministic final reduction and writes the scalar.
__global__ __launch_bounds__(KK, 8)
void masked_loss_onepass(const float* __restrict__ y_true,
                         const float* __restrict__ y_pred,
                         const void*  __restrict__ rows,
                         const void*  __restrict__ cols,
                         float* __restrict__ out)
{
    __shared__ int   sr[KK];
    __shared__ int   sc[KK];
    __shared__ float warp_sums[KK / 32];
    __shared__ bool  s_last;

    const int t = threadIdx.x;   // 0..127
    const int b = blockIdx.x;    // 0..63

    // ---- dtype detection: reference claims int64; JAX x64-off gives int32 ----
    const long long r64 = ((const long long*)rows)[t];
    const long long c64 = ((const long long*)cols)[t];
    const int in_range = (r64 >= 0 && r64 < NN && c64 >= 0 && c64 < NN) ? 1 : 0;
    const int use_i64 = __syncthreads_and(in_range);

    if (use_i64) {
        sr[t] = (int)r64;
        sc[t] = (int)c64;
    } else {
        sr[t] = ((const int*)rows)[t];
        sc[t] = ((const int*)cols)[t];
    }
    __syncthreads();

    const int r = sr[t];
    const int c = sc[t];

    // Issue the gathers FIRST so the dedupe loop hides under DRAM latency.
    const size_t base = (size_t)b * (NN * NN) + (size_t)r * NN + (size_t)c;
    const float vt = __ldg(&y_true[base]);
    const float vp = __ldg(&y_pred[base]);

    // Set semantics: keep only first occurrence of each (r,c) pair.
    int keep = 1;
    for (int j = 0; j < t; ++j) {
        if (sr[j] == r && sc[j] == c) { keep = 0; break; }
    }

    const float d = vt - vp;
    float acc = keep ? d * d : 0.0f;

    // ---- block reduction (4 warps) ----
    #pragma unroll
    for (int off = 16; off > 0; off >>= 1)
        acc += __shfl_xor_sync(0xffffffffu, acc, off);
    if ((t & 31) == 0) warp_sums[t >> 5] = acc;
    __syncthreads();

    if (t == 0) {
        g_partials[b] = warp_sums[0] + warp_sums[1] + warp_sums[2] + warp_sums[3];
        __threadfence();
        const unsigned int ticket = atomicAdd(&g_count, 1u);
        s_last = (ticket == BATCH - 1);
    }
    __syncthreads();

    // ---- last block: deterministic final reduction (fixed order, one warp) ----
    if (s_last && t < 32) {
        __threadfence();  // acquire: make all g_partials visible
        float v = g_partials[t] + g_partials[t + 32];
        #pragma unroll
        for (int off = 16; off > 0; off >>= 1)
            v += __shfl_xor_sync(0xffffffffu, v, off);
        if (t == 0) {
            out[0] = v;
            g_count = 0;   // reset for the next graph replay
        }
    }
}

extern "C" void kernel_launch(void* const* d_in, const int* in_sizes, int n_in,
                              void* d_out, int out_size)
{
    const float* y_true = (const float*)d_in[0];
    const float* y_pred = (const float*)d_in[1];
    masked_loss_onepass<<<BATCH, KK>>>(y_true, y_pred, d_in[2], d_in[3],
                                       (float*)d_out);
}

// round 7
// speedup vs baseline: 1.7731x; 1.3821x over previous
#include <cuda_runtime.h>
#include <cuda_bf16.h>

// Problem constants (from reference: B=64, N=1000, K=128)
static constexpr int BATCH = 64;
static constexpr int NN    = 1000;
static constexpr int KK    = 128;

__device__ float        g_partials[BATCH];
__device__ unsigned int g_count = 0;   // self-resetting ticket counter

// One block per batch. Gather + per-block reduce; the last block to finish
// performs the deterministic final reduction and writes the scalar.
__global__ __launch_bounds__(KK, 8)
void masked_loss_onepass(const float* __restrict__ y_true,
                         const float* __restrict__ y_pred,
                         const void*  __restrict__ rows,
                         const void*  __restrict__ cols,
                         float* __restrict__ out)
{
    __shared__ int   skey[KK];               // (r<<10)|c combined dedupe key
    __shared__ float warp_sums[KK / 32];
    __shared__ bool  s_last;

    const int t = threadIdx.x;   // 0..127
    const int b = blockIdx.x;    // 0..63

    // ---- dtype detection: reference claims int64; JAX x64-off gives int32 ----
    // Load both interpretations up front (independent loads, all in flight).
    const long long r64 = ((const long long*)rows)[t];
    const long long c64 = ((const long long*)cols)[t];
    const int       r32 = ((const int*)rows)[t];
    const int       c32 = ((const int*)cols)[t];

    const int in_range = (r64 >= 0 && r64 < NN && c64 >= 0 && c64 < NN) ? 1 : 0;
    const int use_i64 = __syncthreads_and(in_range);

    const int r = use_i64 ? (int)r64 : r32;
    const int c = use_i64 ? (int)c64 : c32;

    // Issue the gathers IMMEDIATELY — everything below overlaps their latency.
    const size_t base = (size_t)b * (NN * NN) + (size_t)r * NN + (size_t)c;
    const float vt = __ldg(&y_true[base]);
    const float vp = __ldg(&y_pred[base]);

    // Dedupe (set semantics: first occurrence of (r,c) wins), single-key loop.
    const int key = (r << 10) | c;           // bijective: c < 1024
    skey[t] = key;
    __syncthreads();

    int keep = 1;
    for (int j = 0; j < t; ++j) {
        if (skey[j] == key) { keep = 0; break; }
    }

    const float d = vt - vp;
    float acc = keep ? d * d : 0.0f;

    // ---- block reduction (4 warps) ----
    #pragma unroll
    for (int off = 16; off > 0; off >>= 1)
        acc += __shfl_xor_sync(0xffffffffu, acc, off);
    if ((t & 31) == 0) warp_sums[t >> 5] = acc;
    __syncthreads();

    if (t == 0) {
        g_partials[b] = warp_sums[0] + warp_sums[1] + warp_sums[2] + warp_sums[3];
        __threadfence();                                  // release partial
        const unsigned int ticket = atomicAdd(&g_count, 1u);
        s_last = (ticket == BATCH - 1);
    }
    __syncthreads();

    // ---- last block: deterministic final reduction (fixed order, one warp) ----
    if (s_last && t < 32) {
        __threadfence();                                  // acquire ordering
        // L2-forced loads (ld.global.cg): g_partials written by other SMs;
        // avoid any possibility of stale L1 sectors satisfying these reads.
        float v = __ldcg(&g_partials[t]) + __ldcg(&g_partials[t + 32]);
        #pragma unroll
        for (int off = 16; off > 0; off >>= 1)
            v += __shfl_xor_sync(0xffffffffu, v, off);
        if (t == 0) {
            out[0] = v;
            g_count = 0;   // reset for next graph replay (deterministic)
        }
    }
}

extern "C" void kernel_launch(void* const* d_in, const int* in_sizes, int n_in,
                              void* d_out, int out_size)
{
    const float* y_true = (const float*)d_in[0];
    const float* y_pred = (const float*)d_in[1];
    masked_loss_onepass<<<BATCH, KK>>>(y_true, y_pred, d_in[2], d_in[3],
                                       (float*)d_out);
}

// round 10
// speedup vs baseline: 2.1838x; 1.2316x over previous
#include <cuda_runtime.h>
#include <cuda_bf16.h>

// Problem constants (from reference: B=64, N=1000, K=128)
static constexpr int BATCH = 64;
static constexpr int NN    = 1000;
static constexpr int KK    = 128;
static constexpr int TSZ   = 512;      // hash table slots (power of 2)

__device__ float        g_partials[BATCH];
__device__ unsigned int g_count = 0;   // self-resetting ticket counter

__global__ __launch_bounds__(KK, 8)
void masked_loss_onepass(const float* __restrict__ y_true,
                         const float* __restrict__ y_pred,
                         const void*  __restrict__ rows,
                         const void*  __restrict__ cols,
                         float* __restrict__ out)
{
    __shared__ int   tkey[TSZ];             // hash-claim: key per slot (-1 empty)
    __shared__ int   ttid[TSZ];             // min thread-id claiming that key
    __shared__ float warp_sums[KK / 32];
    __shared__ bool  s_last;

    const int t = threadIdx.x;   // 0..127
    const int b = blockIdx.x;    // 0..63

    // ---- issue index loads first (both dtype interpretations, all parallel) ----
    const long long r64 = ((const long long*)rows)[t];
    const long long c64 = ((const long long*)cols)[t];
    const int       r32 = ((const int*)rows)[t];
    const int       c32 = ((const int*)cols)[t];

    // ---- init hash table while index loads are in flight ----
    #pragma unroll
    for (int i = 0; i < TSZ / KK; ++i) {
        tkey[t + i * KK] = -1;
        ttid[t + i * KK] = KK;              // > any tid
    }

    // dtype detection: reference claims int64; JAX x64-off gives int32.
    const int in_range = (r64 >= 0 && r64 < NN && c64 >= 0 && c64 < NN) ? 1 : 0;
    const int use_i64 = __syncthreads_and(in_range);   // also fences table init

    const int r = use_i64 ? (int)r64 : r32;
    const int c = use_i64 ? (int)c64 : c32;

    // ---- issue gathers IMMEDIATELY; dedupe overlaps their latency ----
    const size_t base = (size_t)b * (NN * NN) + (size_t)r * NN + (size_t)c;
    const float vt = __ldg(&y_true[base]);
    const float vp = __ldg(&y_pred[base]);

    // ---- O(1) dedupe via hash claim; min-tid wins => first occurrence,
    //      fully deterministic across replays ----
    const int key = (r << 10) | c;                       // bijective, c < 1024
    int slot = (int)(((unsigned)key * 2654435769u) >> 23) & (TSZ - 1);
    for (;;) {
        const int prev = atomicCAS(&tkey[slot], -1, key);
        if (prev == -1 || prev == key) break;            // installed or shared
        slot = (slot + 1) & (TSZ - 1);                   // linear probe
    }
    atomicMin(&ttid[slot], t);
    __syncthreads();
    const int keep = (ttid[slot] == t);

    const float d = vt - vp;
    float acc = keep ? d * d : 0.0f;

    // ---- block reduction (4 warps) ----
    #pragma unroll
    for (int off = 16; off > 0; off >>= 1)
        acc += __shfl_xor_sync(0xffffffffu, acc, off);
    if ((t & 31) == 0) warp_sums[t >> 5] = acc;
    __syncthreads();

    if (t == 0) {
        g_partials[b] = warp_sums[0] + warp_sums[1] + warp_sums[2] + warp_sums[3];
        __threadfence();                                  // release partial
        const unsigned int ticket = atomicAdd(&g_count, 1u);
        s_last = (ticket == BATCH - 1);
    }
    __syncthreads();

    // ---- last finishing block: deterministic final reduction ----
    if (s_last && t < 32) {
        __threadfence();                                  // acquire ordering
        float v = __ldcg(&g_partials[t]) + __ldcg(&g_partials[t + 32]);
        #pragma unroll
        for (int off = 16; off > 0; off >>= 1)
            v += __shfl_xor_sync(0xffffffffu, v, off);
        if (t == 0) {
            out[0] = v;
            g_count = 0;   // reset for next graph replay (deterministic)
        }
    }
}

extern "C" void kernel_launch(void* const* d_in, const int* in_sizes, int n_in,
                              void* d_out, int out_size)
{
    const float* y_true = (const float*)d_in[0];
    const float* y_pred = (const float*)d_in[1];
    masked_loss_onepass<<<BATCH, KK>>>(y_true, y_pred, d_in[2], d_in[3],
                                       (float*)d_out);
}